// round 1
// baseline (speedup 1.0000x reference)
#include <cuda_runtime.h>
#include <math.h>
#include <stdint.h>

typedef unsigned long long ull;

#define T_STEPS 128
#define BATCH   32
#define NHID    1024
#define NH2     2048
#define NTOK    10000
#define TB      (T_STEPS*BATCH)   /* 4096 */

// ---------------- device scratch (no allocations allowed) ----------------
__device__ float g_emb[TB*NHID];        // 16 MB  gathered embeddings
__device__ float g_xw0[TB*NH2];         // 32 MB  precomputed x @ W0[:1024,:]
__device__ float g_hidden[TB*NHID];     // 16 MB  per-step hidden states
__device__ float g_states[9][BATCH*NHID];

// genotype: edge e reads states[c_ein[e]], writes states[e+1]
__constant__ int c_ein[8] = {0,1,1,1,2,5,3,5};
// act: 0 sigmoid, 1 relu, 2 tanh, 3 identity
__constant__ int c_act[8] = {0,1,1,3,2,0,2,1};

__device__ __forceinline__ float sigf(float x){ return 1.0f/(1.0f+expf(-x)); }
__device__ __forceinline__ float actf(int a, float x){
  if(a==0) return sigf(x);
  if(a==1) return fmaxf(x,0.0f);
  if(a==2) return tanhf(x);
  return x;
}

// packed fp32x2 FMA (Blackwell): d.lo += a.lo*b.lo ; d.hi += a.hi*b.hi
__device__ __forceinline__ void fma2(ull& d, ull a, ull b){
  asm("fma.rn.f32x2 %0, %1, %2, %0;" : "+l"(d) : "l"(a), "l"(b));
}
__device__ __forceinline__ ull dupf(float x){
  ull r; unsigned u = __float_as_uint(x);
  asm("mov.b64 %0, {%1, %1};" : "=l"(r) : "r"(u));
  return r;
}
__device__ __forceinline__ float lo2(ull v){ return __uint_as_float((unsigned)(v & 0xffffffffull)); }
__device__ __forceinline__ float hi2(ull v){ return __uint_as_float((unsigned)(v >> 32)); }
__device__ __forceinline__ float sum2(ull v){ return lo2(v) + hi2(v); }

// ---------------- embedding gather ----------------
__global__ void k_embed(const int* __restrict__ tok, const float* __restrict__ encW){
  const int tb = blockIdx.x;
  const int t  = tok[tb];
  const float4* s = reinterpret_cast<const float4*>(encW + (size_t)t*NHID);
  float4* d = reinterpret_cast<float4*>(g_emb + (size_t)tb*NHID);
  d[threadIdx.x] = s[threadIdx.x];      // 256 threads * float4 = 1024 floats
}

// ---------------- hoisted GEMM: g_xw0 = emb(4096x1024) @ W0[0:1024,:](1024x2048) ----
__global__ void k_xw0(const float* __restrict__ W0){
  __shared__ float As[16][68];
  __shared__ float Bs[16][68];
  const int tid = threadIdx.x;
  const int m0 = blockIdx.y*64, n0 = blockIdx.x*64;
  const int ty = tid>>4, tx = tid&15;
  float acc[4][4] = {};
  for(int k0=0;k0<NHID;k0+=16){
    { int r = tid>>2, q = (tid&3)<<2;
      const float4 v = *reinterpret_cast<const float4*>(&g_emb[(size_t)(m0+r)*NHID + k0 + q]);
      As[q+0][r]=v.x; As[q+1][r]=v.y; As[q+2][r]=v.z; As[q+3][r]=v.w; }
    { int r = tid>>4, q = (tid&15)<<2;
      const float4 v = *reinterpret_cast<const float4*>(&W0[(size_t)(k0+r)*NH2 + n0 + q]);
      *reinterpret_cast<float4*>(&Bs[r][q]) = v; }
    __syncthreads();
    #pragma unroll
    for(int kk=0;kk<16;kk++){
      const float4 a = *reinterpret_cast<const float4*>(&As[kk][ty<<2]);
      const float4 b = *reinterpret_cast<const float4*>(&Bs[kk][tx<<2]);
      acc[0][0]+=a.x*b.x; acc[0][1]+=a.x*b.y; acc[0][2]+=a.x*b.z; acc[0][3]+=a.x*b.w;
      acc[1][0]+=a.y*b.x; acc[1][1]+=a.y*b.y; acc[1][2]+=a.y*b.z; acc[1][3]+=a.y*b.w;
      acc[2][0]+=a.z*b.x; acc[2][1]+=a.z*b.y; acc[2][2]+=a.z*b.z; acc[2][3]+=a.z*b.w;
      acc[3][0]+=a.w*b.x; acc[3][1]+=a.w*b.y; acc[3][2]+=a.w*b.z; acc[3][3]+=a.w*b.w;
    }
    __syncthreads();
  }
  #pragma unroll
  for(int i=0;i<4;i++)
    #pragma unroll
    for(int j=0;j<4;j++)
      g_xw0[(size_t)(m0+(ty<<2)+i)*NH2 + n0+(tx<<2)+j] = acc[i][j];
}

// ---------------- cell init: states[0] -------------------------------------
// s = h_prev + sigmoid(c0)*(tanh(h0) - h_prev),
// [c0|h0] = xw0[t] + h_prev @ W0[1024:2048,:]
__global__ void k_cell0(const float* __restrict__ W0, const float* __restrict__ h0in, int t){
  __shared__ float sh[32][68];
  __shared__ float wct[16][68];
  __shared__ float wht[16][68];
  const int tid = threadIdx.x;
  const int j0 = blockIdx.x<<4;         // 64 blocks * 16 cols
  const int jj = tid & 15;
  const int mg = tid >> 4;              // rows mg and mg+16
  const float* __restrict__ hprev = (t==0) ? h0in : (g_hidden + (size_t)(t-1)*BATCH*NHID);

  ull aC0=0, aC1=0, aH0=0, aH1=0;
  for(int k0=0;k0<NHID;k0+=64){
    #pragma unroll
    for(int it=0;it<2;it++){
      const int li = tid + (it<<8);
      const int r = li>>4, q = (li&15)<<2;
      const float4 v = *reinterpret_cast<const float4*>(&hprev[(size_t)r*NHID + k0 + q]);
      *reinterpret_cast<float4*>(&sh[r][q]) = v;
    }
    {
      const int rb = tid>>4;
      #pragma unroll
      for(int rr=0;rr<4;rr++){
        const int r = rb + (rr<<4);
        const float* wrow = &W0[(size_t)(NHID + k0 + r)*NH2 + j0];
        wct[jj][r] = wrow[jj];
        wht[jj][r] = wrow[NHID + jj];
      }
    }
    __syncthreads();
    #pragma unroll
    for(int kk=0;kk<64;kk+=4){
      const ulonglong2 a0 = *reinterpret_cast<const ulonglong2*>(&sh[mg][kk]);
      const ulonglong2 a1 = *reinterpret_cast<const ulonglong2*>(&sh[mg+16][kk]);
      const ulonglong2 wc = *reinterpret_cast<const ulonglong2*>(&wct[jj][kk]);
      const ulonglong2 wh = *reinterpret_cast<const ulonglong2*>(&wht[jj][kk]);
      fma2(aC0, a0.x, wc.x); fma2(aC0, a0.y, wc.y);
      fma2(aH0, a0.x, wh.x); fma2(aH0, a0.y, wh.y);
      fma2(aC1, a1.x, wc.x); fma2(aC1, a1.y, wc.y);
      fma2(aH1, a1.x, wh.x); fma2(aH1, a1.y, wh.y);
    }
    __syncthreads();
  }
  const int col = j0 + jj;
  const size_t xb = ((size_t)t*BATCH)*NH2;
  #pragma unroll
  for(int mi=0; mi<2; mi++){
    const int m = mg + mi*16;
    const float c = (mi ? sum2(aC1) : sum2(aC0)) + g_xw0[xb + (size_t)m*NH2 + col];
    const float h = (mi ? sum2(aH1) : sum2(aH0)) + g_xw0[xb + (size_t)m*NH2 + NHID + col];
    const float hp = hprev[(size_t)m*NHID + col];
    g_states[0][(size_t)m*NHID + col] = hp + sigf(c)*(tanhf(h)-hp);
  }
}

// ---------------- genotype edge(s): one level per launch -------------------
__global__ void k_edge(const float* __restrict__ Ws, int4 eids){
  int e;
  if      (blockIdx.y==0) e = eids.x;
  else if (blockIdx.y==1) e = eids.y;
  else if (blockIdx.y==2) e = eids.z;
  else                    e = eids.w;
  const int ein = c_ein[e];
  const int act = c_act[e];
  const float* __restrict__ sp = g_states[ein];
  float* __restrict__ outp = g_states[e+1];
  const float* __restrict__ W = Ws + (size_t)e*NHID*NH2;

  __shared__ float sh[32][68];
  __shared__ float wct[16][68];
  __shared__ float wht[16][68];
  const int tid = threadIdx.x;
  const int j0 = blockIdx.x<<4;
  const int jj = tid & 15;
  const int mg = tid >> 4;

  ull aC0=0, aC1=0, aH0=0, aH1=0;
  for(int k0=0;k0<NHID;k0+=64){
    #pragma unroll
    for(int it=0;it<2;it++){
      const int li = tid + (it<<8);
      const int r = li>>4, q = (li&15)<<2;
      const float4 v = *reinterpret_cast<const float4*>(&sp[(size_t)r*NHID + k0 + q]);
      *reinterpret_cast<float4*>(&sh[r][q]) = v;
    }
    {
      const int rb = tid>>4;
      #pragma unroll
      for(int rr=0;rr<4;rr++){
        const int r = rb + (rr<<4);
        const float* wrow = &W[(size_t)(k0 + r)*NH2 + j0];
        wct[jj][r] = wrow[jj];
        wht[jj][r] = wrow[NHID + jj];
      }
    }
    __syncthreads();
    #pragma unroll
    for(int kk=0;kk<64;kk+=4){
      const ulonglong2 a0 = *reinterpret_cast<const ulonglong2*>(&sh[mg][kk]);
      const ulonglong2 a1 = *reinterpret_cast<const ulonglong2*>(&sh[mg+16][kk]);
      const ulonglong2 wc = *reinterpret_cast<const ulonglong2*>(&wct[jj][kk]);
      const ulonglong2 wh = *reinterpret_cast<const ulonglong2*>(&wht[jj][kk]);
      fma2(aC0, a0.x, wc.x); fma2(aC0, a0.y, wc.y);
      fma2(aH0, a0.x, wh.x); fma2(aH0, a0.y, wh.y);
      fma2(aC1, a1.x, wc.x); fma2(aC1, a1.y, wc.y);
      fma2(aH1, a1.x, wh.x); fma2(aH1, a1.y, wh.y);
    }
    __syncthreads();
  }
  const int col = j0 + jj;
  #pragma unroll
  for(int mi=0; mi<2; mi++){
    const int m = mg + mi*16;
    const float c = (mi ? sum2(aC1) : sum2(aC0));
    const float h = (mi ? sum2(aH1) : sum2(aH0));
    const float spv = sp[(size_t)m*NHID + col];
    outp[(size_t)m*NHID + col] = spv + sigf(c)*(actf(act,h)-spv);
  }
}

// ---------------- mean of states 1..8 -> hidden[t] -------------------------
__global__ void k_mean(int t){
  const int i = blockIdx.x*256 + threadIdx.x;
  float s = g_states[1][i];
  #pragma unroll
  for(int e=2;e<9;e++) s += g_states[e][i];
  g_hidden[(size_t)t*BATCH*NHID + i] = s*0.125f;
}

// ---------------- decoder: logits = hidden(4096x1024) @ encW^T + dec_b -----
// block tile 128(m) x 64(n), thread tile 8m x 4n, fp32x2 packed along m-pairs
__global__ void k_dec(const float* __restrict__ encW, const float* __restrict__ decb,
                      float* __restrict__ out){
  __shared__ float As[16][136];
  __shared__ float Bs[16][68];
  const int tid = threadIdx.x;
  const int m0 = blockIdx.y*128, n0 = blockIdx.x*64;
  const int mg = tid>>4;           // 0..15 -> m subtile of 8
  const int ng = tid&15;           // 0..15 -> n subtile of 4
  const int m0t = mg<<3, n0t = ng<<2;

  ull acc[4][4];
  #pragma unroll
  for(int p=0;p<4;p++)
    #pragma unroll
    for(int n=0;n<4;n++) acc[p][n] = 0ull;

  for(int k0=0;k0<NHID;k0+=16){
    #pragma unroll
    for(int it=0;it<2;it++){
      const int li = tid + (it<<8);         // 0..511 float4 units
      const int r = li>>2, q = (li&3)<<2;
      const float4 v = *reinterpret_cast<const float4*>(&g_hidden[(size_t)(m0+r)*NHID + k0 + q]);
      As[q+0][r]=v.x; As[q+1][r]=v.y; As[q+2][r]=v.z; As[q+3][r]=v.w;
    }
    {
      const int r = tid>>2, q = (tid&3)<<2;
      const int n = n0 + r;
      float4 v = make_float4(0.f,0.f,0.f,0.f);
      if(n < NTOK) v = *reinterpret_cast<const float4*>(&encW[(size_t)n*NHID + k0 + q]);
      Bs[q+0][r]=v.x; Bs[q+1][r]=v.y; Bs[q+2][r]=v.z; Bs[q+3][r]=v.w;
    }
    __syncthreads();
    #pragma unroll
    for(int kk=0;kk<16;kk++){
      const ulonglong2 a01 = *reinterpret_cast<const ulonglong2*>(&As[kk][m0t]);
      const ulonglong2 a23 = *reinterpret_cast<const ulonglong2*>(&As[kk][m0t+4]);
      const float4 b = *reinterpret_cast<const float4*>(&Bs[kk][n0t]);
      const ull b0 = dupf(b.x), b1 = dupf(b.y), b2 = dupf(b.z), b3 = dupf(b.w);
      fma2(acc[0][0], a01.x, b0); fma2(acc[0][1], a01.x, b1);
      fma2(acc[0][2], a01.x, b2); fma2(acc[0][3], a01.x, b3);
      fma2(acc[1][0], a01.y, b0); fma2(acc[1][1], a01.y, b1);
      fma2(acc[1][2], a01.y, b2); fma2(acc[1][3], a01.y, b3);
      fma2(acc[2][0], a23.x, b0); fma2(acc[2][1], a23.x, b1);
      fma2(acc[2][2], a23.x, b2); fma2(acc[2][3], a23.x, b3);
      fma2(acc[3][0], a23.y, b0); fma2(acc[3][1], a23.y, b1);
      fma2(acc[3][2], a23.y, b2); fma2(acc[3][3], a23.y, b3);
    }
    __syncthreads();
  }
  #pragma unroll
  for(int p=0;p<4;p++){
    const int m = m0 + m0t + (p<<1);
    #pragma unroll
    for(int nn=0;nn<4;nn++){
      const int n_ = n0 + n0t + nn;
      if(n_ < NTOK){
        const float bias = decb[n_];
        out[(size_t)m*NTOK + n_]       = lo2(acc[p][nn]) + bias;
        out[(size_t)(m+1)*NTOK + n_]   = hi2(acc[p][nn]) + bias;
      }
    }
  }
}

// ---------------- in-place log_softmax over each row of 10000 --------------
__global__ void k_lsm(float* __restrict__ out){
  const int row = blockIdx.x;
  float* p = out + (size_t)row*NTOK;
  __shared__ float red[256];
  float mx = -1e30f;
  for(int i=threadIdx.x;i<NTOK;i+=256) mx = fmaxf(mx, p[i]);
  red[threadIdx.x] = mx; __syncthreads();
  for(int s=128;s>0;s>>=1){
    if(threadIdx.x<s) red[threadIdx.x] = fmaxf(red[threadIdx.x], red[threadIdx.x+s]);
    __syncthreads();
  }
  mx = red[0]; __syncthreads();
  float sum = 0.f;
  for(int i=threadIdx.x;i<NTOK;i+=256) sum += expf(p[i]-mx);
  red[threadIdx.x] = sum; __syncthreads();
  for(int s=128;s>0;s>>=1){
    if(threadIdx.x<s) red[threadIdx.x] += red[threadIdx.x+s];
    __syncthreads();
  }
  const float lse = mx + logf(red[0]);
  for(int i=threadIdx.x;i<NTOK;i+=256) p[i] = p[i] - lse;
}

// ---------------- h_last copy ----------------------------------------------
__global__ void k_hlast(float* __restrict__ out){
  float4* d = reinterpret_cast<float4*>(out + (size_t)TB*NTOK);
  const float4* s = reinterpret_cast<const float4*>(g_hidden + (size_t)(T_STEPS-1)*BATCH*NHID);
  const int i = blockIdx.x*256 + threadIdx.x;
  d[i] = s[i];
}

// ---------------- launch ----------------------------------------------------
extern "C" void kernel_launch(void* const* d_in, const int* in_sizes, int n_in,
                              void* d_out, int out_size){
  const int*   tokens = (const int*)  d_in[0];
  const float* h0     = (const float*)d_in[1];
  const float* encW   = (const float*)d_in[2];
  const float* W0     = (const float*)d_in[3];
  const float* Ws     = (const float*)d_in[4];
  const float* decb   = (const float*)d_in[5];
  float* out = (float*)d_out;

  k_embed<<<TB, 256>>>(tokens, encW);
  k_xw0<<<dim3(NH2/64, TB/64), 256>>>(W0);

  for(int t=0;t<T_STEPS;t++){
    k_cell0<<<64, 256>>>(W0, h0, t);
    k_edge<<<dim3(64,1), 256>>>(Ws, make_int4(0,0,0,0));   // level 1: e0
    k_edge<<<dim3(64,3), 256>>>(Ws, make_int4(1,2,3,0));   // level 2: e1,e2,e3
    k_edge<<<dim3(64,2), 256>>>(Ws, make_int4(4,6,0,0));   // level 3: e4,e6
    k_edge<<<dim3(64,2), 256>>>(Ws, make_int4(5,7,0,0));   // level 4: e5,e7
    k_mean<<<(BATCH*NHID)/256, 256>>>(t);
  }

  k_dec<<<dim3((NTOK+63)/64, TB/128), 256>>>(encW, decb, out);
  k_lsm<<<TB, 256>>>(out);
  k_hlast<<<(BATCH*NHID/4)/256, 256>>>(out);
}

// round 2
// speedup vs baseline: 1.0077x; 1.0077x over previous
#include <cuda_runtime.h>
#include <math.h>
#include <stdint.h>

typedef unsigned long long ull;

#define T_STEPS 128
#define BATCH   32
#define NHID    1024
#define NH2     2048
#define NTOK    10000
#define TB      (T_STEPS*BATCH)   /* 4096 */

// ---------------- device scratch (no allocations allowed) ----------------
__device__ float g_emb[TB*NHID];        // 16 MB  gathered embeddings
__device__ float g_xw0[TB*NH2];         // 32 MB  precomputed x @ W0[:1024,:]
__device__ float g_hidden[TB*NHID];     // 16 MB  per-step hidden states
__device__ float g_states[9][BATCH*NHID];

// genotype: edge e reads states[c_ein[e]], writes states[e+1]
__constant__ int c_ein[8] = {0,1,1,1,2,5,3,5};
// act: 0 sigmoid, 1 relu, 2 tanh, 3 identity
__constant__ int c_act[8] = {0,1,1,3,2,0,2,1};

__device__ __forceinline__ float sigf(float x){ return 1.0f/(1.0f+expf(-x)); }
__device__ __forceinline__ float actf(int a, float x){
  if(a==0) return sigf(x);
  if(a==1) return fmaxf(x,0.0f);
  if(a==2) return tanhf(x);
  return x;
}

// packed fp32x2 FMA (Blackwell): d.lo += a.lo*b.lo ; d.hi += a.hi*b.hi
__device__ __forceinline__ void fma2(ull& d, ull a, ull b){
  asm("fma.rn.f32x2 %0, %1, %2, %0;" : "+l"(d) : "l"(a), "l"(b));
}
__device__ __forceinline__ ull dupf(float x){
  ull r; unsigned u = __float_as_uint(x);
  asm("mov.b64 %0, {%1, %1};" : "=l"(r) : "r"(u));
  return r;
}
__device__ __forceinline__ float lo2(ull v){ return __uint_as_float((unsigned)(v & 0xffffffffull)); }
__device__ __forceinline__ float hi2(ull v){ return __uint_as_float((unsigned)(v >> 32)); }
__device__ __forceinline__ float sum2(ull v){ return lo2(v) + hi2(v); }

// ---------------- embedding gather ----------------
__global__ void k_embed(const int* __restrict__ tok, const float* __restrict__ encW){
  const int tb = blockIdx.x;
  const int t  = tok[tb];
  const float4* s = reinterpret_cast<const float4*>(encW + (size_t)t*NHID);
  float4* d = reinterpret_cast<float4*>(g_emb + (size_t)tb*NHID);
  d[threadIdx.x] = s[threadIdx.x];      // 256 threads * float4 = 1024 floats
}

// ---------------- hoisted GEMM: g_xw0 = emb(4096x1024) @ W0[0:1024,:](1024x2048) ----
__global__ void k_xw0(const float* __restrict__ W0){
  __shared__ float As[16][68];
  __shared__ float Bs[16][68];
  const int tid = threadIdx.x;
  const int m0 = blockIdx.y*64, n0 = blockIdx.x*64;
  const int ty = tid>>4, tx = tid&15;
  float acc[4][4] = {};
  for(int k0=0;k0<NHID;k0+=16){
    { int r = tid>>2, q = (tid&3)<<2;
      const float4 v = *reinterpret_cast<const float4*>(&g_emb[(size_t)(m0+r)*NHID + k0 + q]);
      As[q+0][r]=v.x; As[q+1][r]=v.y; As[q+2][r]=v.z; As[q+3][r]=v.w; }
    { int r = tid>>4, q = (tid&15)<<2;
      const float4 v = *reinterpret_cast<const float4*>(&W0[(size_t)(k0+r)*NH2 + n0 + q]);
      *reinterpret_cast<float4*>(&Bs[r][q]) = v; }
    __syncthreads();
    #pragma unroll
    for(int kk=0;kk<16;kk++){
      const float4 a = *reinterpret_cast<const float4*>(&As[kk][ty<<2]);
      const float4 b = *reinterpret_cast<const float4*>(&Bs[kk][tx<<2]);
      acc[0][0]+=a.x*b.x; acc[0][1]+=a.x*b.y; acc[0][2]+=a.x*b.z; acc[0][3]+=a.x*b.w;
      acc[1][0]+=a.y*b.x; acc[1][1]+=a.y*b.y; acc[1][2]+=a.y*b.z; acc[1][3]+=a.y*b.w;
      acc[2][0]+=a.z*b.x; acc[2][1]+=a.z*b.y; acc[2][2]+=a.z*b.z; acc[2][3]+=a.z*b.w;
      acc[3][0]+=a.w*b.x; acc[3][1]+=a.w*b.y; acc[3][2]+=a.w*b.z; acc[3][3]+=a.w*b.w;
    }
    __syncthreads();
  }
  #pragma unroll
  for(int i=0;i<4;i++)
    #pragma unroll
    for(int j=0;j<4;j++)
      g_xw0[(size_t)(m0+(ty<<2)+i)*NH2 + n0+(tx<<2)+j] = acc[i][j];
}

// ---------------- cell init: states[0] -------------------------------------
// s = h_prev + sigmoid(c0)*(tanh(h0) - h_prev),
// [c0|h0] = xw0[t] + h_prev @ W0[1024:2048,:]
__global__ void k_cell0(const float* __restrict__ W0, const float* __restrict__ h0in, int t){
  __shared__ float sh[32][68];
  __shared__ float wct[16][68];
  __shared__ float wht[16][68];
  const int tid = threadIdx.x;
  const int j0 = blockIdx.x<<4;         // 64 blocks * 16 cols
  const int jj = tid & 15;
  const int mg = tid >> 4;              // rows mg and mg+16
  const float* __restrict__ hprev = (t==0) ? h0in : (g_hidden + (size_t)(t-1)*BATCH*NHID);

  ull aC0=0, aC1=0, aH0=0, aH1=0;
  for(int k0=0;k0<NHID;k0+=64){
    #pragma unroll
    for(int it=0;it<2;it++){
      const int li = tid + (it<<8);
      const int r = li>>4, q = (li&15)<<2;
      const float4 v = *reinterpret_cast<const float4*>(&hprev[(size_t)r*NHID + k0 + q]);
      *reinterpret_cast<float4*>(&sh[r][q]) = v;
    }
    {
      const int rb = tid>>4;
      #pragma unroll
      for(int rr=0;rr<4;rr++){
        const int r = rb + (rr<<4);
        const float* wrow = &W0[(size_t)(NHID + k0 + r)*NH2 + j0];
        wct[jj][r] = wrow[jj];
        wht[jj][r] = wrow[NHID + jj];
      }
    }
    __syncthreads();
    #pragma unroll
    for(int kk=0;kk<64;kk+=4){
      const ulonglong2 a0 = *reinterpret_cast<const ulonglong2*>(&sh[mg][kk]);
      const ulonglong2 a1 = *reinterpret_cast<const ulonglong2*>(&sh[mg+16][kk]);
      const ulonglong2 wc = *reinterpret_cast<const ulonglong2*>(&wct[jj][kk]);
      const ulonglong2 wh = *reinterpret_cast<const ulonglong2*>(&wht[jj][kk]);
      fma2(aC0, a0.x, wc.x); fma2(aC0, a0.y, wc.y);
      fma2(aH0, a0.x, wh.x); fma2(aH0, a0.y, wh.y);
      fma2(aC1, a1.x, wc.x); fma2(aC1, a1.y, wc.y);
      fma2(aH1, a1.x, wh.x); fma2(aH1, a1.y, wh.y);
    }
    __syncthreads();
  }
  const int col = j0 + jj;
  const size_t xb = ((size_t)t*BATCH)*NH2;
  #pragma unroll
  for(int mi=0; mi<2; mi++){
    const int m = mg + mi*16;
    const float c = (mi ? sum2(aC1) : sum2(aC0)) + g_xw0[xb + (size_t)m*NH2 + col];
    const float h = (mi ? sum2(aH1) : sum2(aH0)) + g_xw0[xb + (size_t)m*NH2 + NHID + col];
    const float hp = hprev[(size_t)m*NHID + col];
    g_states[0][(size_t)m*NHID + col] = hp + sigf(c)*(tanhf(h)-hp);
  }
}

// ---------------- genotype edge(s): one level per launch -------------------
__global__ void k_edge(const float* __restrict__ Ws, int4 eids){
  int e;
  if      (blockIdx.y==0) e = eids.x;
  else if (blockIdx.y==1) e = eids.y;
  else if (blockIdx.y==2) e = eids.z;
  else                    e = eids.w;
  const int ein = c_ein[e];
  const int act = c_act[e];
  const float* __restrict__ sp = g_states[ein];
  float* __restrict__ outp = g_states[e+1];
  const float* __restrict__ W = Ws + (size_t)e*NHID*NH2;

  __shared__ float sh[32][68];
  __shared__ float wct[16][68];
  __shared__ float wht[16][68];
  const int tid = threadIdx.x;
  const int j0 = blockIdx.x<<4;
  const int jj = tid & 15;
  const int mg = tid >> 4;

  ull aC0=0, aC1=0, aH0=0, aH1=0;
  for(int k0=0;k0<NHID;k0+=64){
    #pragma unroll
    for(int it=0;it<2;it++){
      const int li = tid + (it<<8);
      const int r = li>>4, q = (li&15)<<2;
      const float4 v = *reinterpret_cast<const float4*>(&sp[(size_t)r*NHID + k0 + q]);
      *reinterpret_cast<float4*>(&sh[r][q]) = v;
    }
    {
      const int rb = tid>>4;
      #pragma unroll
      for(int rr=0;rr<4;rr++){
        const int r = rb + (rr<<4);
        const float* wrow = &W[(size_t)(k0 + r)*NH2 + j0];
        wct[jj][r] = wrow[jj];
        wht[jj][r] = wrow[NHID + jj];
      }
    }
    __syncthreads();
    #pragma unroll
    for(int kk=0;kk<64;kk+=4){
      const ulonglong2 a0 = *reinterpret_cast<const ulonglong2*>(&sh[mg][kk]);
      const ulonglong2 a1 = *reinterpret_cast<const ulonglong2*>(&sh[mg+16][kk]);
      const ulonglong2 wc = *reinterpret_cast<const ulonglong2*>(&wct[jj][kk]);
      const ulonglong2 wh = *reinterpret_cast<const ulonglong2*>(&wht[jj][kk]);
      fma2(aC0, a0.x, wc.x); fma2(aC0, a0.y, wc.y);
      fma2(aH0, a0.x, wh.x); fma2(aH0, a0.y, wh.y);
      fma2(aC1, a1.x, wc.x); fma2(aC1, a1.y, wc.y);
      fma2(aH1, a1.x, wh.x); fma2(aH1, a1.y, wh.y);
    }
    __syncthreads();
  }
  const int col = j0 + jj;
  #pragma unroll
  for(int mi=0; mi<2; mi++){
    const int m = mg + mi*16;
    const float c = (mi ? sum2(aC1) : sum2(aC0));
    const float h = (mi ? sum2(aH1) : sum2(aH0));
    const float spv = sp[(size_t)m*NHID + col];
    outp[(size_t)m*NHID + col] = spv + sigf(c)*(actf(act,h)-spv);
  }
}

// ---------------- mean of states 1..8 -> hidden[t] -------------------------
__global__ void k_mean(int t){
  const int i = blockIdx.x*256 + threadIdx.x;
  float s = g_states[1][i];
  #pragma unroll
  for(int e=2;e<9;e++) s += g_states[e][i];
  g_hidden[(size_t)t*BATCH*NHID + i] = s*0.125f;
}

// ---------------- decoder: logits = hidden(4096x1024) @ encW^T + dec_b -----
// block tile 128(m) x 64(n), thread tile 8m x 4n, fp32x2 packed along m-pairs
__global__ void k_dec(const float* __restrict__ encW, const float* __restrict__ decb,
                      float* __restrict__ out){
  __shared__ float As[16][136];
  __shared__ float Bs[16][68];
  const int tid = threadIdx.x;
  const int m0 = blockIdx.y*128, n0 = blockIdx.x*64;
  const int mg = tid>>4;           // 0..15 -> m subtile of 8
  const int ng = tid&15;           // 0..15 -> n subtile of 4
  const int m0t = mg<<3, n0t = ng<<2;

  ull acc[4][4];
  #pragma unroll
  for(int p=0;p<4;p++)
    #pragma unroll
    for(int n=0;n<4;n++) acc[p][n] = 0ull;

  for(int k0=0;k0<NHID;k0+=16){
    #pragma unroll
    for(int it=0;it<2;it++){
      const int li = tid + (it<<8);         // 0..511 float4 units
      const int r = li>>2, q = (li&3)<<2;
      const float4 v = *reinterpret_cast<const float4*>(&g_hidden[(size_t)(m0+r)*NHID + k0 + q]);
      As[q+0][r]=v.x; As[q+1][r]=v.y; As[q+2][r]=v.z; As[q+3][r]=v.w;
    }
    {
      const int r = tid>>2, q = (tid&3)<<2;
      const int n = n0 + r;
      float4 v = make_float4(0.f,0.f,0.f,0.f);
      if(n < NTOK) v = *reinterpret_cast<const float4*>(&encW[(size_t)n*NHID + k0 + q]);
      Bs[q+0][r]=v.x; Bs[q+1][r]=v.y; Bs[q+2][r]=v.z; Bs[q+3][r]=v.w;
    }
    __syncthreads();
    #pragma unroll
    for(int kk=0;kk<16;kk++){
      const ulonglong2 a01 = *reinterpret_cast<const ulonglong2*>(&As[kk][m0t]);
      const ulonglong2 a23 = *reinterpret_cast<const ulonglong2*>(&As[kk][m0t+4]);
      const float4 b = *reinterpret_cast<const float4*>(&Bs[kk][n0t]);
      const ull b0 = dupf(b.x), b1 = dupf(b.y), b2 = dupf(b.z), b3 = dupf(b.w);
      fma2(acc[0][0], a01.x, b0); fma2(acc[0][1], a01.x, b1);
      fma2(acc[0][2], a01.x, b2); fma2(acc[0][3], a01.x, b3);
      fma2(acc[1][0], a01.y, b0); fma2(acc[1][1], a01.y, b1);
      fma2(acc[1][2], a01.y, b2); fma2(acc[1][3], a01.y, b3);
      fma2(acc[2][0], a23.x, b0); fma2(acc[2][1], a23.x, b1);
      fma2(acc[2][2], a23.x, b2); fma2(acc[2][3], a23.x, b3);
      fma2(acc[3][0], a23.y, b0); fma2(acc[3][1], a23.y, b1);
      fma2(acc[3][2], a23.y, b2); fma2(acc[3][3], a23.y, b3);
    }
    __syncthreads();
  }
  #pragma unroll
  for(int p=0;p<4;p++){
    const int m = m0 + m0t + (p<<1);
    #pragma unroll
    for(int nn=0;nn<4;nn++){
      const int n_ = n0 + n0t + nn;
      if(n_ < NTOK){
        const float bias = decb[n_];
        out[(size_t)m*NTOK + n_]       = lo2(acc[p][nn]) + bias;
        out[(size_t)(m+1)*NTOK + n_]   = hi2(acc[p][nn]) + bias;
      }
    }
  }
}

// ---------------- in-place log_softmax over each row of 10000 --------------
__global__ void k_lsm(float* __restrict__ out){
  const int row = blockIdx.x;
  float* p = out + (size_t)row*NTOK;
  __shared__ float red[256];
  float mx = -1e30f;
  for(int i=threadIdx.x;i<NTOK;i+=256) mx = fmaxf(mx, p[i]);
  red[threadIdx.x] = mx; __syncthreads();
  for(int s=128;s>0;s>>=1){
    if(threadIdx.x<s) red[threadIdx.x] = fmaxf(red[threadIdx.x], red[threadIdx.x+s]);
    __syncthreads();
  }
  mx = red[0]; __syncthreads();
  float sum = 0.f;
  for(int i=threadIdx.x;i<NTOK;i+=256) sum += expf(p[i]-mx);
  red[threadIdx.x] = sum; __syncthreads();
  for(int s=128;s>0;s>>=1){
    if(threadIdx.x<s) red[threadIdx.x] += red[threadIdx.x+s];
    __syncthreads();
  }
  const float lse = mx + logf(red[0]);
  for(int i=threadIdx.x;i<NTOK;i+=256) p[i] = p[i] - lse;
}

// ---------------- h_last copy ----------------------------------------------
__global__ void k_hlast(float* __restrict__ out){
  float4* d = reinterpret_cast<float4*>(out + (size_t)TB*NTOK);
  const float4* s = reinterpret_cast<const float4*>(g_hidden + (size_t)(T_STEPS-1)*BATCH*NHID);
  const int i = blockIdx.x*256 + threadIdx.x;
  d[i] = s[i];
}

// ---------------- launch ----------------------------------------------------
extern "C" void kernel_launch(void* const* d_in, const int* in_sizes, int n_in,
                              void* d_out, int out_size){
  const int*   tokens = (const int*)  d_in[0];
  const float* h0     = (const float*)d_in[1];
  const float* encW   = (const float*)d_in[2];
  const float* W0     = (const float*)d_in[3];
  const float* Ws     = (const float*)d_in[4];
  const float* decb   = (const float*)d_in[5];
  float* out = (float*)d_out;

  k_embed<<<TB, 256>>>(tokens, encW);
  k_xw0<<<dim3(NH2/64, TB/64), 256>>>(W0);

  for(int t=0;t<T_STEPS;t++){
    k_cell0<<<64, 256>>>(W0, h0, t);
    k_edge<<<dim3(64,1), 256>>>(Ws, make_int4(0,0,0,0));   // level 1: e0
    k_edge<<<dim3(64,3), 256>>>(Ws, make_int4(1,2,3,0));   // level 2: e1,e2,e3
    k_edge<<<dim3(64,2), 256>>>(Ws, make_int4(4,6,0,0));   // level 3: e4,e6
    k_edge<<<dim3(64,2), 256>>>(Ws, make_int4(5,7,0,0));   // level 4: e5,e7
    k_mean<<<(BATCH*NHID)/256, 256>>>(t);
  }

  k_dec<<<dim3((NTOK+63)/64, TB/128), 256>>>(encW, decb, out);
  k_lsm<<<TB, 256>>>(out);
  k_hlast<<<(BATCH*NHID/4)/256, 256>>>(out);
}

// round 3
// speedup vs baseline: 1.0092x; 1.0015x over previous
#include <cuda_runtime.h>
#include <math.h>
#include <stdint.h>

typedef unsigned long long ull;

#define T_STEPS 128
#define BATCH   32
#define NHID    1024
#define NH2     2048
#define NTOK    10000
#define TB      (T_STEPS*BATCH)   /* 4096 */

// ---------------- device scratch (no allocations allowed) ----------------
__device__ float g_emb[TB*NHID];        // 16 MB  gathered embeddings
__device__ float g_xw0[TB*NH2];         // 32 MB  precomputed x @ W0[:1024,:]
__device__ float g_hidden[TB*NHID];     // 16 MB  per-step hidden states
__device__ float g_states[9][BATCH*NHID];

// genotype: edge e reads states[c_ein[e]], writes states[e+1]
__constant__ int c_ein[8] = {0,1,1,1,2,5,3,5};
// act: 0 sigmoid, 1 relu, 2 tanh, 3 identity
__constant__ int c_act[8] = {0,1,1,3,2,0,2,1};

__device__ __forceinline__ float sigf(float x){ return 1.0f/(1.0f+expf(-x)); }
__device__ __forceinline__ float actf(int a, float x){
  if(a==0) return sigf(x);
  if(a==1) return fmaxf(x,0.0f);
  if(a==2) return tanhf(x);
  return x;
}

// packed fp32x2 FMA (Blackwell): d.lo += a.lo*b.lo ; d.hi += a.hi*b.hi
__device__ __forceinline__ void fma2(ull& d, ull a, ull b){
  asm("fma.rn.f32x2 %0, %1, %2, %0;" : "+l"(d) : "l"(a), "l"(b));
}
__device__ __forceinline__ ull dupf(float x){
  ull r; unsigned u = __float_as_uint(x);
  asm("mov.b64 %0, {%1, %1};" : "=l"(r) : "r"(u));
  return r;
}
__device__ __forceinline__ float lo2(ull v){ return __uint_as_float((unsigned)(v & 0xffffffffull)); }
__device__ __forceinline__ float hi2(ull v){ return __uint_as_float((unsigned)(v >> 32)); }
__device__ __forceinline__ float sum2(ull v){ return lo2(v) + hi2(v); }

// ---------------- embedding gather ----------------
__global__ void k_embed(const int* __restrict__ tok, const float* __restrict__ encW){
  const int tb = blockIdx.x;
  const int t  = tok[tb];
  const float4* s = reinterpret_cast<const float4*>(encW + (size_t)t*NHID);
  float4* d = reinterpret_cast<float4*>(g_emb + (size_t)tb*NHID);
  d[threadIdx.x] = s[threadIdx.x];      // 256 threads * float4 = 1024 floats
}

// ---------------- hoisted GEMM: g_xw0 = emb(4096x1024) @ W0[0:1024,:](1024x2048) ----
__global__ void k_xw0(const float* __restrict__ W0){
  __shared__ float As[16][68];
  __shared__ float Bs[16][68];
  const int tid = threadIdx.x;
  const int m0 = blockIdx.y*64, n0 = blockIdx.x*64;
  const int ty = tid>>4, tx = tid&15;
  float acc[4][4] = {};
  for(int k0=0;k0<NHID;k0+=16){
    { int r = tid>>2, q = (tid&3)<<2;
      const float4 v = *reinterpret_cast<const float4*>(&g_emb[(size_t)(m0+r)*NHID + k0 + q]);
      As[q+0][r]=v.x; As[q+1][r]=v.y; As[q+2][r]=v.z; As[q+3][r]=v.w; }
    { int r = tid>>4, q = (tid&15)<<2;
      const float4 v = *reinterpret_cast<const float4*>(&W0[(size_t)(k0+r)*NH2 + n0 + q]);
      *reinterpret_cast<float4*>(&Bs[r][q]) = v; }
    __syncthreads();
    #pragma unroll
    for(int kk=0;kk<16;kk++){
      const float4 a = *reinterpret_cast<const float4*>(&As[kk][ty<<2]);
      const float4 b = *reinterpret_cast<const float4*>(&Bs[kk][tx<<2]);
      acc[0][0]+=a.x*b.x; acc[0][1]+=a.x*b.y; acc[0][2]+=a.x*b.z; acc[0][3]+=a.x*b.w;
      acc[1][0]+=a.y*b.x; acc[1][1]+=a.y*b.y; acc[1][2]+=a.y*b.z; acc[1][3]+=a.y*b.w;
      acc[2][0]+=a.z*b.x; acc[2][1]+=a.z*b.y; acc[2][2]+=a.z*b.z; acc[2][3]+=a.z*b.w;
      acc[3][0]+=a.w*b.x; acc[3][1]+=a.w*b.y; acc[3][2]+=a.w*b.z; acc[3][3]+=a.w*b.w;
    }
    __syncthreads();
  }
  #pragma unroll
  for(int i=0;i<4;i++)
    #pragma unroll
    for(int j=0;j<4;j++)
      g_xw0[(size_t)(m0+(ty<<2)+i)*NH2 + n0+(tx<<2)+j] = acc[i][j];
}

// ---------------- cell init: states[0] -------------------------------------
// s = h_prev + sigmoid(c0)*(tanh(h0) - h_prev),
// [c0|h0] = xw0[t] + h_prev @ W0[1024:2048,:]
__global__ void k_cell0(const float* __restrict__ W0, const float* __restrict__ h0in, int t){
  __shared__ float sh[32][68];
  __shared__ float wct[16][68];
  __shared__ float wht[16][68];
  const int tid = threadIdx.x;
  const int j0 = blockIdx.x<<4;         // 64 blocks * 16 cols
  const int jj = tid & 15;
  const int mg = tid >> 4;              // rows mg and mg+16
  const float* __restrict__ hprev = (t==0) ? h0in : (g_hidden + (size_t)(t-1)*BATCH*NHID);

  ull aC0=0, aC1=0, aH0=0, aH1=0;
  for(int k0=0;k0<NHID;k0+=64){
    #pragma unroll
    for(int it=0;it<2;it++){
      const int li = tid + (it<<8);
      const int r = li>>4, q = (li&15)<<2;
      const float4 v = *reinterpret_cast<const float4*>(&hprev[(size_t)r*NHID + k0 + q]);
      *reinterpret_cast<float4*>(&sh[r][q]) = v;
    }
    {
      const int rb = tid>>4;
      #pragma unroll
      for(int rr=0;rr<4;rr++){
        const int r = rb + (rr<<4);
        const float* wrow = &W0[(size_t)(NHID + k0 + r)*NH2 + j0];
        wct[jj][r] = wrow[jj];
        wht[jj][r] = wrow[NHID + jj];
      }
    }
    __syncthreads();
    #pragma unroll
    for(int kk=0;kk<64;kk+=4){
      const ulonglong2 a0 = *reinterpret_cast<const ulonglong2*>(&sh[mg][kk]);
      const ulonglong2 a1 = *reinterpret_cast<const ulonglong2*>(&sh[mg+16][kk]);
      const ulonglong2 wc = *reinterpret_cast<const ulonglong2*>(&wct[jj][kk]);
      const ulonglong2 wh = *reinterpret_cast<const ulonglong2*>(&wht[jj][kk]);
      fma2(aC0, a0.x, wc.x); fma2(aC0, a0.y, wc.y);
      fma2(aH0, a0.x, wh.x); fma2(aH0, a0.y, wh.y);
      fma2(aC1, a1.x, wc.x); fma2(aC1, a1.y, wc.y);
      fma2(aH1, a1.x, wh.x); fma2(aH1, a1.y, wh.y);
    }
    __syncthreads();
  }
  const int col = j0 + jj;
  const size_t xb = ((size_t)t*BATCH)*NH2;
  #pragma unroll
  for(int mi=0; mi<2; mi++){
    const int m = mg + mi*16;
    const float c = (mi ? sum2(aC1) : sum2(aC0)) + g_xw0[xb + (size_t)m*NH2 + col];
    const float h = (mi ? sum2(aH1) : sum2(aH0)) + g_xw0[xb + (size_t)m*NH2 + NHID + col];
    const float hp = hprev[(size_t)m*NHID + col];
    g_states[0][(size_t)m*NHID + col] = hp + sigf(c)*(tanhf(h)-hp);
  }
}

// ---------------- genotype edge(s): one level per launch -------------------
__global__ void k_edge(const float* __restrict__ Ws, int4 eids){
  int e;
  if      (blockIdx.y==0) e = eids.x;
  else if (blockIdx.y==1) e = eids.y;
  else if (blockIdx.y==2) e = eids.z;
  else                    e = eids.w;
  const int ein = c_ein[e];
  const int act = c_act[e];
  const float* __restrict__ sp = g_states[ein];
  float* __restrict__ outp = g_states[e+1];
  const float* __restrict__ W = Ws + (size_t)e*NHID*NH2;

  __shared__ float sh[32][68];
  __shared__ float wct[16][68];
  __shared__ float wht[16][68];
  const int tid = threadIdx.x;
  const int j0 = blockIdx.x<<4;
  const int jj = tid & 15;
  const int mg = tid >> 4;

  ull aC0=0, aC1=0, aH0=0, aH1=0;
  for(int k0=0;k0<NHID;k0+=64){
    #pragma unroll
    for(int it=0;it<2;it++){
      const int li = tid + (it<<8);
      const int r = li>>4, q = (li&15)<<2;
      const float4 v = *reinterpret_cast<const float4*>(&sp[(size_t)r*NHID + k0 + q]);
      *reinterpret_cast<float4*>(&sh[r][q]) = v;
    }
    {
      const int rb = tid>>4;
      #pragma unroll
      for(int rr=0;rr<4;rr++){
        const int r = rb + (rr<<4);
        const float* wrow = &W[(size_t)(k0 + r)*NH2 + j0];
        wct[jj][r] = wrow[jj];
        wht[jj][r] = wrow[NHID + jj];
      }
    }
    __syncthreads();
    #pragma unroll
    for(int kk=0;kk<64;kk+=4){
      const ulonglong2 a0 = *reinterpret_cast<const ulonglong2*>(&sh[mg][kk]);
      const ulonglong2 a1 = *reinterpret_cast<const ulonglong2*>(&sh[mg+16][kk]);
      const ulonglong2 wc = *reinterpret_cast<const ulonglong2*>(&wct[jj][kk]);
      const ulonglong2 wh = *reinterpret_cast<const ulonglong2*>(&wht[jj][kk]);
      fma2(aC0, a0.x, wc.x); fma2(aC0, a0.y, wc.y);
      fma2(aH0, a0.x, wh.x); fma2(aH0, a0.y, wh.y);
      fma2(aC1, a1.x, wc.x); fma2(aC1, a1.y, wc.y);
      fma2(aH1, a1.x, wh.x); fma2(aH1, a1.y, wh.y);
    }
    __syncthreads();
  }
  const int col = j0 + jj;
  #pragma unroll
  for(int mi=0; mi<2; mi++){
    const int m = mg + mi*16;
    const float c = (mi ? sum2(aC1) : sum2(aC0));
    const float h = (mi ? sum2(aH1) : sum2(aH0));
    const float spv = sp[(size_t)m*NHID + col];
    outp[(size_t)m*NHID + col] = spv + sigf(c)*(actf(act,h)-spv);
  }
}

// ---------------- mean of states 1..8 -> hidden[t] -------------------------
__global__ void k_mean(int t){
  const int i = blockIdx.x*256 + threadIdx.x;
  float s = g_states[1][i];
  #pragma unroll
  for(int e=2;e<9;e++) s += g_states[e][i];
  g_hidden[(size_t)t*BATCH*NHID + i] = s*0.125f;
}

// ---------------- decoder: logits = hidden(4096x1024) @ encW^T + dec_b -----
// block tile 128(m) x 64(n), thread tile 8m x 4n, fp32x2 packed along m-pairs
__global__ void k_dec(const float* __restrict__ encW, const float* __restrict__ decb,
                      float* __restrict__ out){
  __shared__ float As[16][136];
  __shared__ float Bs[16][68];
  const int tid = threadIdx.x;
  const int m0 = blockIdx.y*128, n0 = blockIdx.x*64;
  const int mg = tid>>4;           // 0..15 -> m subtile of 8
  const int ng = tid&15;           // 0..15 -> n subtile of 4
  const int m0t = mg<<3, n0t = ng<<2;

  ull acc[4][4];
  #pragma unroll
  for(int p=0;p<4;p++)
    #pragma unroll
    for(int n=0;n<4;n++) acc[p][n] = 0ull;

  for(int k0=0;k0<NHID;k0+=16){
    #pragma unroll
    for(int it=0;it<2;it++){
      const int li = tid + (it<<8);         // 0..511 float4 units
      const int r = li>>2, q = (li&3)<<2;
      const float4 v = *reinterpret_cast<const float4*>(&g_hidden[(size_t)(m0+r)*NHID + k0 + q]);
      As[q+0][r]=v.x; As[q+1][r]=v.y; As[q+2][r]=v.z; As[q+3][r]=v.w;
    }
    {
      const int r = tid>>2, q = (tid&3)<<2;
      const int n = n0 + r;
      float4 v = make_float4(0.f,0.f,0.f,0.f);
      if(n < NTOK) v = *reinterpret_cast<const float4*>(&encW[(size_t)n*NHID + k0 + q]);
      Bs[q+0][r]=v.x; Bs[q+1][r]=v.y; Bs[q+2][r]=v.z; Bs[q+3][r]=v.w;
    }
    __syncthreads();
    #pragma unroll
    for(int kk=0;kk<16;kk++){
      const ulonglong2 a01 = *reinterpret_cast<const ulonglong2*>(&As[kk][m0t]);
      const ulonglong2 a23 = *reinterpret_cast<const ulonglong2*>(&As[kk][m0t+4]);
      const float4 b = *reinterpret_cast<const float4*>(&Bs[kk][n0t]);
      const ull b0 = dupf(b.x), b1 = dupf(b.y), b2 = dupf(b.z), b3 = dupf(b.w);
      fma2(acc[0][0], a01.x, b0); fma2(acc[0][1], a01.x, b1);
      fma2(acc[0][2], a01.x, b2); fma2(acc[0][3], a01.x, b3);
      fma2(acc[1][0], a01.y, b0); fma2(acc[1][1], a01.y, b1);
      fma2(acc[1][2], a01.y, b2); fma2(acc[1][3], a01.y, b3);
      fma2(acc[2][0], a23.x, b0); fma2(acc[2][1], a23.x, b1);
      fma2(acc[2][2], a23.x, b2); fma2(acc[2][3], a23.x, b3);
      fma2(acc[3][0], a23.y, b0); fma2(acc[3][1], a23.y, b1);
      fma2(acc[3][2], a23.y, b2); fma2(acc[3][3], a23.y, b3);
    }
    __syncthreads();
  }
  #pragma unroll
  for(int p=0;p<4;p++){
    const int m = m0 + m0t + (p<<1);
    #pragma unroll
    for(int nn=0;nn<4;nn++){
      const int n_ = n0 + n0t + nn;
      if(n_ < NTOK){
        const float bias = decb[n_];
        out[(size_t)m*NTOK + n_]       = lo2(acc[p][nn]) + bias;
        out[(size_t)(m+1)*NTOK + n_]   = hi2(acc[p][nn]) + bias;
      }
    }
  }
}

// ---------------- in-place log_softmax over each row of 10000 --------------
__global__ void k_lsm(float* __restrict__ out){
  const int row = blockIdx.x;
  float* p = out + (size_t)row*NTOK;
  __shared__ float red[256];
  float mx = -1e30f;
  for(int i=threadIdx.x;i<NTOK;i+=256) mx = fmaxf(mx, p[i]);
  red[threadIdx.x] = mx; __syncthreads();
  for(int s=128;s>0;s>>=1){
    if(threadIdx.x<s) red[threadIdx.x] = fmaxf(red[threadIdx.x], red[threadIdx.x+s]);
    __syncthreads();
  }
  mx = red[0]; __syncthreads();
  float sum = 0.f;
  for(int i=threadIdx.x;i<NTOK;i+=256) sum += expf(p[i]-mx);
  red[threadIdx.x] = sum; __syncthreads();
  for(int s=128;s>0;s>>=1){
    if(threadIdx.x<s) red[threadIdx.x] += red[threadIdx.x+s];
    __syncthreads();
  }
  const float lse = mx + logf(red[0]);
  for(int i=threadIdx.x;i<NTOK;i+=256) p[i] = p[i] - lse;
}

// ---------------- h_last copy ----------------------------------------------
__global__ void k_hlast(float* __restrict__ out){
  float4* d = reinterpret_cast<float4*>(out + (size_t)TB*NTOK);
  const float4* s = reinterpret_cast<const float4*>(g_hidden + (size_t)(T_STEPS-1)*BATCH*NHID);
  const int i = blockIdx.x*256 + threadIdx.x;
  d[i] = s[i];
}

// ---------------- launch ----------------------------------------------------
extern "C" void kernel_launch(void* const* d_in, const int* in_sizes, int n_in,
                              void* d_out, int out_size){
  const int*   tokens = (const int*)  d_in[0];
  const float* h0     = (const float*)d_in[1];
  const float* encW   = (const float*)d_in[2];
  const float* W0     = (const float*)d_in[3];
  const float* Ws     = (const float*)d_in[4];
  const float* decb   = (const float*)d_in[5];
  float* out = (float*)d_out;

  k_embed<<<TB, 256>>>(tokens, encW);
  k_xw0<<<dim3(NH2/64, TB/64), 256>>>(W0);

  for(int t=0;t<T_STEPS;t++){
    k_cell0<<<64, 256>>>(W0, h0, t);
    k_edge<<<dim3(64,1), 256>>>(Ws, make_int4(0,0,0,0));   // level 1: e0
    k_edge<<<dim3(64,3), 256>>>(Ws, make_int4(1,2,3,0));   // level 2: e1,e2,e3
    k_edge<<<dim3(64,2), 256>>>(Ws, make_int4(4,6,0,0));   // level 3: e4,e6
    k_edge<<<dim3(64,2), 256>>>(Ws, make_int4(5,7,0,0));   // level 4: e5,e7
    k_mean<<<(BATCH*NHID)/256, 256>>>(t);
  }

  k_dec<<<dim3((NTOK+63)/64, TB/128), 256>>>(encW, decb, out);
  k_lsm<<<TB, 256>>>(out);
  k_hlast<<<(BATCH*NHID/4)/256, 256>>>(out);
}